// round 2
// baseline (speedup 1.0000x reference)
#include <cuda_runtime.h>

typedef unsigned long long ull;

// Broadcast-packed coefficients: g_re[ch*9+k] = (re,re), g_im = (im,im)
__device__ ull g_re[144];
__device__ ull g_im[144];

__device__ __forceinline__ ull pack2(float a, float b) {
    ull r;
    asm("mov.b64 %0, {%1, %2};" : "=l"(r) : "f"(a), "f"(b));
    return r;
}
__device__ __forceinline__ void unpack2(ull v, float& a, float& b) {
    asm("mov.b64 {%0, %1}, %2;" : "=f"(a), "=f"(b) : "l"(v));
}
__device__ __forceinline__ void ffma2(ull& d, ull a, ull b) {
    asm("fma.rn.f32x2 %0, %1, %2, %0;" : "+l"(d) : "l"(a), "l"(b));
}
__device__ __forceinline__ ull fmul2(ull a, ull b) {
    ull r;
    asm("mul.rn.f32x2 %0, %1, %2;" : "=l"(r) : "l"(a), "l"(b));
    return r;
}
__device__ __forceinline__ ull fadd2(ull a, ull b) {
    ull r;
    asm("add.rn.f32x2 %0, %1, %2;" : "=l"(r) : "l"(a), "l"(b));
    return r;
}
__device__ __forceinline__ ull ffma2v(ull a, ull b, ull c) {
    ull r;
    asm("fma.rn.f32x2 %0, %1, %2, %3;" : "=l"(r) : "l"(a), "l"(b), "l"(c));
    return r;
}

// ---------------------------------------------------------------------------
// Setup: build the 16x16 StronglyEntanglingLayers unitary from weights (2,4,3).
// Warp 0 computes the 8 single-qubit Rot gates (2 sincos each) into smem;
// all 256 threads then do the kron + 16^3 matmul + CNOT permutations.
// ---------------------------------------------------------------------------
__global__ void build_unitary_kernel(const float* __restrict__ w) {
    __shared__ float2 gates[8][4];
    __shared__ float2 cur[16][16];
    __shared__ float2 Lm[16][16];
    __shared__ float2 tmp[16][16];
    int t = threadIdx.x;
    int i = t >> 4, j = t & 15;

    if (t < 32) {
        int g = t >> 2, e = t & 3;
        int bi = e >> 1, bj = e & 1;
        float phi = w[g * 3 + 0];
        float th  = w[g * 3 + 1];
        float om  = w[g * 3 + 2];
        float sh, chf;
        sincosf(0.5f * th, &sh, &chf);
        float mag, phs;
        if (!bi && !bj)      { mag =  chf; phs = -0.5f * (phi + om); }
        else if (!bi &&  bj) { mag = -sh;  phs =  0.5f * (phi - om); }
        else if ( bi && !bj) { mag =  sh;  phs = -0.5f * (phi - om); }
        else                 { mag =  chf; phs =  0.5f * (phi + om); }
        float sp, cp;
        sincosf(phs, &sp, &cp);
        gates[g][e] = make_float2(mag * cp, mag * sp);
    }
    cur[i][j] = make_float2(i == j ? 1.f : 0.f, 0.f);
    __syncthreads();

#pragma unroll 1
    for (int l = 0; l < 2; l++) {
        // kron of 4 gates; wire 0 = MSB
        float2 v = make_float2(1.f, 0.f);
#pragma unroll
        for (int wi = 0; wi < 4; wi++) {
            int bi = (i >> (3 - wi)) & 1;
            int bj = (j >> (3 - wi)) & 1;
            float2 e = gates[l * 4 + wi][bi * 2 + bj];
            v = make_float2(v.x * e.x - v.y * e.y, v.x * e.y + v.y * e.x);
        }
        Lm[i][j] = v;
        __syncthreads();

        // tmp = Lm @ cur
        float2 acc = make_float2(0.f, 0.f);
#pragma unroll
        for (int k = 0; k < 16; k++) {
            float2 a = Lm[i][k], b = cur[k][j];
            acc.x += a.x * b.x - a.y * b.y;
            acc.y += a.x * b.y + a.y * b.x;
        }
        tmp[i][j] = acc;
        __syncthreads();

        // CNOT ring as composed row permutation
        int r = (l % 3) + 1;
        int q = i;
#pragma unroll
        for (int m = 3; m >= 0; m--) {
            int tt = (m + r) & 3;
            int cb = 1 << (3 - m), tb = 1 << (3 - tt);
            if (q & cb) q ^= tb;
        }
        cur[i][j] = tmp[q][j];
        __syncthreads();
    }

    if (j < 9) {
        float2 u = cur[i][j];
        g_re[i * 9 + j] = pack2(u.x, u.x);
        g_im[i * 9 + j] = pack2(u.y, u.y);
    }
}

// ---------------------------------------------------------------------------
// Main kernel. Each thread: 4(x) x 2(y) pixel quad, all 16 channels.
// f32x2 lanes hold two horizontally-adjacent pixels; re and im accumulate
// in separate packed registers. Block 64x4, grid (1, 32, 32).
// out[b][ch][y][x] = min(8 * |U_ch . p|^2 / ||p||^2, 1)
// ---------------------------------------------------------------------------
__global__ __launch_bounds__(256, 3)
void qconv_kernel(const float* __restrict__ x, float* __restrict__ out) {
    __shared__ ull sRe[144];
    __shared__ ull sIm[144];
    int tid = threadIdx.y * 64 + threadIdx.x;
    if (tid < 144) {
        sRe[tid] = g_re[tid];
        sIm[tid] = g_im[tid];
    }
    __syncthreads();

    const int b  = blockIdx.z;
    const int x0 = threadIdx.x * 4;                       // 0..252
    const int r0 = blockIdx.y * 8 + threadIdx.y * 2;      // 0..254

    const float* xin = x + (size_t)b * 65536;

    // Load 4 rows (r0-1..r0+2) x 6 cols (x0-1..x0+4), pad = 0.01,
    // directly building overlapping packed pairs pp[i][s] = (v[s], v[s+1]).
    ull pp[4][5];
#pragma unroll
    for (int i = 0; i < 4; i++) {
        float v0, v1, v2, v3, v4, v5;
        int ry = r0 - 1 + i;
        if (ry >= 0 && ry < 256) {
            const float* rp = xin + ry * 256;
            float4 q = *(const float4*)(rp + x0);
            v1 = q.x; v2 = q.y; v3 = q.z; v4 = q.w;
            v0 = (x0 > 0)   ? rp[x0 - 1] : 0.01f;
            v5 = (x0 < 252) ? rp[x0 + 4] : 0.01f;
        } else {
            v0 = v1 = v2 = v3 = v4 = v5 = 0.01f;
        }
        pp[i][0] = pack2(v0, v1);
        pp[i][1] = pack2(v1, v2);
        pp[i][2] = pack2(v2, v3);
        pp[i][3] = pack2(v3, v4);
        pp[i][4] = pack2(v4, v5);
    }

    // ||p||^2 per pixel-pair via packed separable sums.
    // hp[i][q] = packed horizontal 3-tap sum of squares for col pair (2q,2q+1)
    ull sp[2][2];
    {
        ull hp[4][2];
#pragma unroll
        for (int i = 0; i < 4; i++) {
            ull sq0 = fmul2(pp[i][0], pp[i][0]);
            ull sq1 = fmul2(pp[i][1], pp[i][1]);
            ull sq2 = fmul2(pp[i][2], pp[i][2]);
            ull sq3 = fmul2(pp[i][3], pp[i][3]);
            ull sq4 = fmul2(pp[i][4], pp[i][4]);
            hp[i][0] = fadd2(fadd2(sq0, sq1), sq2);
            hp[i][1] = fadd2(fadd2(sq2, sq3), sq4);
        }
#pragma unroll
        for (int r = 0; r < 2; r++)
#pragma unroll
            for (int q = 0; q < 2; q++)
                sp[r][q] = fadd2(fadd2(hp[r][q], hp[r + 1][q]), hp[r + 2][q]);
    }
    // invp[r][q] = packed 8/max(s,1e-24)
    ull invp[2][2];
#pragma unroll
    for (int r = 0; r < 2; r++)
#pragma unroll
        for (int q = 0; q < 2; q++) {
            float s0, s1;
            unpack2(sp[r][q], s0, s1);
            float i0 = __fdividef(8.0f, fmaxf(s0, 1e-24f));
            float i1 = __fdividef(8.0f, fmaxf(s1, 1e-24f));
            invp[r][q] = pack2(i0, i1);
        }

    float* ob = out + (size_t)b * 16 * 65536 + (size_t)r0 * 256 + x0;

#pragma unroll 1
    for (int ch = 0; ch < 16; ch++) {
        ull are[2][2], aim[2][2];
#pragma unroll
        for (int r = 0; r < 2; r++)
#pragma unroll
            for (int q = 0; q < 2; q++) { are[r][q] = 0ULL; aim[r][q] = 0ULL; }

#pragma unroll
        for (int k = 0; k < 9; k++) {
            const int dr = k / 3, dc = k % 3;
            ull cre = sRe[ch * 9 + k];
            ull cim = sIm[ch * 9 + k];
#pragma unroll
            for (int r = 0; r < 2; r++)
#pragma unroll
                for (int q = 0; q < 2; q++) {
                    ull p = pp[r + dr][2 * q + dc];
                    ffma2(are[r][q], cre, p);
                    ffma2(aim[r][q], cim, p);
                }
        }

#pragma unroll
        for (int r = 0; r < 2; r++) {
            float res[4];
#pragma unroll
            for (int q = 0; q < 2; q++) {
                ull mag = fmul2(are[r][q], are[r][q]);
                mag = ffma2v(aim[r][q], aim[r][q], mag);
                ull sc = fmul2(mag, invp[r][q]);
                float f0, f1;
                unpack2(sc, f0, f1);
                res[2 * q]     = fminf(f0, 1.0f);
                res[2 * q + 1] = fminf(f1, 1.0f);
            }
            *(float4*)(ob + (size_t)ch * 65536 + (size_t)r * 256) =
                make_float4(res[0], res[1], res[2], res[3]);
        }
    }
}

extern "C" void kernel_launch(void* const* d_in, const int* in_sizes, int n_in,
                              void* d_out, int out_size) {
    const float* x = (const float*)d_in[0];        // (32,1,256,256) fp32
    const float* w = (const float*)d_in[1];        // (2,4,3) fp32
    float* out = (float*)d_out;                    // (32,16,256,256) fp32

    build_unitary_kernel<<<1, 256>>>(w);

    dim3 block(64, 4, 1);
    dim3 grid(1, 32, 32);
    qconv_kernel<<<grid, block>>>(x, out);
}

// round 3
// speedup vs baseline: 1.1830x; 1.1830x over previous
#include <cuda_runtime.h>

typedef unsigned long long ull;

// Packed complex coefficients U[ch][k], ch=0..15, k=0..8 (re,im) as f32x2
__device__ ull g_coef[144];

__device__ __forceinline__ ull pack2(float a, float b) {
    ull r;
    asm("mov.b64 %0, {%1, %2};" : "=l"(r) : "f"(a), "f"(b));
    return r;
}
__device__ __forceinline__ void unpack2(ull v, float& a, float& b) {
    asm("mov.b64 {%0, %1}, %2;" : "=f"(a), "=f"(b) : "l"(v));
}
__device__ __forceinline__ void ffma2(ull& d, ull a, ull b) {
    asm("fma.rn.f32x2 %0, %1, %2, %0;" : "+l"(d) : "l"(a), "l"(b));
}
__device__ __forceinline__ ull fmul2(ull a, ull b) {
    ull r;
    asm("mul.rn.f32x2 %0, %1, %2;" : "=l"(r) : "l"(a), "l"(b));
    return r;
}

// ---------------------------------------------------------------------------
// Setup: build the 16x16 StronglyEntanglingLayers unitary from weights (2,4,3).
// Warp 0 computes the 8 Rot gates via MUFU sincos; 256 threads do the
// kron + 16^3 complex matmul + CNOT row permutations.
// ---------------------------------------------------------------------------
__global__ void build_unitary_kernel(const float* __restrict__ w) {
    __shared__ float2 gates[8][4];
    __shared__ float2 cur[16][16];
    __shared__ float2 Lm[16][16];
    __shared__ float2 tmp[16][16];
    int t = threadIdx.x;
    int i = t >> 4, j = t & 15;

    if (t < 32) {
        int g = t >> 2, e = t & 3;
        int bi = e >> 1, bj = e & 1;
        float phi = w[g * 3 + 0];
        float th  = w[g * 3 + 1];
        float om  = w[g * 3 + 2];
        float sh, chf;
        __sincosf(0.5f * th, &sh, &chf);
        float mag, phs;
        if (!bi && !bj)      { mag =  chf; phs = -0.5f * (phi + om); }
        else if (!bi &&  bj) { mag = -sh;  phs =  0.5f * (phi - om); }
        else if ( bi && !bj) { mag =  sh;  phs = -0.5f * (phi - om); }
        else                 { mag =  chf; phs =  0.5f * (phi + om); }
        float sp, cp;
        __sincosf(phs, &sp, &cp);
        gates[g][e] = make_float2(mag * cp, mag * sp);
    }
    cur[i][j] = make_float2(i == j ? 1.f : 0.f, 0.f);
    __syncthreads();

#pragma unroll 1
    for (int l = 0; l < 2; l++) {
        float2 v = make_float2(1.f, 0.f);
#pragma unroll
        for (int wi = 0; wi < 4; wi++) {
            int bi = (i >> (3 - wi)) & 1;
            int bj = (j >> (3 - wi)) & 1;
            float2 e = gates[l * 4 + wi][bi * 2 + bj];
            v = make_float2(v.x * e.x - v.y * e.y, v.x * e.y + v.y * e.x);
        }
        Lm[i][j] = v;
        __syncthreads();

        float2 acc = make_float2(0.f, 0.f);
#pragma unroll
        for (int k = 0; k < 16; k++) {
            float2 a = Lm[i][k], b = cur[k][j];
            acc.x += a.x * b.x - a.y * b.y;
            acc.y += a.x * b.y + a.y * b.x;
        }
        tmp[i][j] = acc;
        __syncthreads();

        int r = (l % 3) + 1;
        int q = i;
#pragma unroll
        for (int m = 3; m >= 0; m--) {
            int tt = (m + r) & 3;
            int cb = 1 << (3 - m), tb = 1 << (3 - tt);
            if (q & cb) q ^= tb;
        }
        cur[i][j] = tmp[q][j];
        __syncthreads();
    }

    if (j < 9) {
        float2 u = cur[i][j];
        g_coef[i * 9 + j] = pack2(u.x, u.y);
    }
}

// ---------------------------------------------------------------------------
// Main kernel. Each thread: 4(x) x 2(y) pixel quad, all 16 channels.
// acc registers hold (re,im) packed per pixel; patch values broadcast-packed.
// Block 64x4, grid (1, 32, 32).
// out[b][ch][y][x] = min(8 * |U_ch . p|^2 / ||p||^2, 1)
// ---------------------------------------------------------------------------
__global__ __launch_bounds__(256, 4)
void qconv_kernel(const float* __restrict__ x, float* __restrict__ out) {
    __shared__ ull sW[144];
    int tid = threadIdx.y * 64 + threadIdx.x;
    if (tid < 144) sW[tid] = g_coef[tid];
    __syncthreads();

    const int b  = blockIdx.z;
    const int x0 = threadIdx.x * 4;                       // 0..252
    const int r0 = blockIdx.y * 8 + threadIdx.y * 2;      // 0..254

    const float* xin = x + (size_t)b * 65536;

    // Load 4 rows (r0-1 .. r0+2) x 6 cols (x0-1 .. x0+4), pad = 0.01
    float v[4][6];
#pragma unroll
    for (int i = 0; i < 4; i++) {
        int ry = r0 - 1 + i;
        if (ry >= 0 && ry < 256) {
            const float* rp = xin + ry * 256;
            float4 q = *(const float4*)(rp + x0);
            v[i][1] = q.x; v[i][2] = q.y; v[i][3] = q.z; v[i][4] = q.w;
            v[i][0] = (x0 > 0)   ? rp[x0 - 1] : 0.01f;
            v[i][5] = (x0 < 252) ? rp[x0 + 4] : 0.01f;
        } else {
#pragma unroll
            for (int c = 0; c < 6; c++) v[i][c] = 0.01f;
        }
    }

    // ||p||^2 per pixel via separable row sums; invp packed per pixel pair
    ull invp[2][2];
    {
        float h[4][4];
#pragma unroll
        for (int i = 0; i < 4; i++) {
            float sq[6];
#pragma unroll
            for (int c = 0; c < 6; c++) sq[c] = v[i][c] * v[i][c];
#pragma unroll
            for (int c = 0; c < 4; c++) h[i][c] = sq[c] + sq[c + 1] + sq[c + 2];
        }
#pragma unroll
        for (int r = 0; r < 2; r++)
#pragma unroll
            for (int q = 0; q < 2; q++) {
                float s0 = h[r][2 * q]     + h[r + 1][2 * q]     + h[r + 2][2 * q];
                float s1 = h[r][2 * q + 1] + h[r + 1][2 * q + 1] + h[r + 2][2 * q + 1];
                float i0 = __fdividef(8.0f, fmaxf(s0, 1e-24f));
                float i1 = __fdividef(8.0f, fmaxf(s1, 1e-24f));
                invp[r][q] = pack2(i0, i1);
            }
    }

    // Broadcast-packed patch values for f32x2 FMAs
    ull pp[4][6];
#pragma unroll
    for (int i = 0; i < 4; i++)
#pragma unroll
        for (int c = 0; c < 6; c++) pp[i][c] = pack2(v[i][c], v[i][c]);

    float* ob = out + (size_t)b * 16 * 65536 + (size_t)r0 * 256 + x0;

#pragma unroll 1
    for (int ch = 0; ch < 16; ch++) {
        ull acc[2][4];
#pragma unroll
        for (int r = 0; r < 2; r++)
#pragma unroll
            for (int c = 0; c < 4; c++) acc[r][c] = 0ULL;

#pragma unroll
        for (int k = 0; k < 9; k++) {
            const int dr = k / 3, dc = k % 3;
            ull cf = sW[ch * 9 + k];
#pragma unroll
            for (int r = 0; r < 2; r++)
#pragma unroll
                for (int c = 0; c < 4; c++)
                    ffma2(acc[r][c], cf, pp[r + dr][c + dc]);
        }

#pragma unroll
        for (int r = 0; r < 2; r++) {
            float res[4];
#pragma unroll
            for (int q = 0; q < 2; q++) {
                // |acc|^2 for two pixels, then one packed multiply by inv
                ull m0 = fmul2(acc[r][2 * q],     acc[r][2 * q]);
                ull m1 = fmul2(acc[r][2 * q + 1], acc[r][2 * q + 1]);
                float a0, b0, a1, b1;
                unpack2(m0, a0, b0);
                unpack2(m1, a1, b1);
                ull mags = pack2(a0 + b0, a1 + b1);
                ull sc = fmul2(mags, invp[r][q]);
                float f0, f1;
                unpack2(sc, f0, f1);
                res[2 * q]     = fminf(f0, 1.0f);
                res[2 * q + 1] = fminf(f1, 1.0f);
            }
            *(float4*)(ob + (size_t)ch * 65536 + (size_t)r * 256) =
                make_float4(res[0], res[1], res[2], res[3]);
        }
    }
}

extern "C" void kernel_launch(void* const* d_in, const int* in_sizes, int n_in,
                              void* d_out, int out_size) {
    const float* x = (const float*)d_in[0];        // (32,1,256,256) fp32
    const float* w = (const float*)d_in[1];        // (2,4,3) fp32
    float* out = (float*)d_out;                    // (32,16,256,256) fp32

    build_unitary_kernel<<<1, 256>>>(w);

    dim3 block(64, 4, 1);
    dim3 grid(1, 32, 32);
    qconv_kernel<<<grid, block>>>(x, out);
}